// round 1
// baseline (speedup 1.0000x reference)
#include <cuda_runtime.h>
#include <math.h>

#define BB 8192
#define NN 4096
#define WBINS 1000
#define LSTRIDE 101      // L_CUTOFF + 1, row stride of sine_terms
#define LL 16            // truncated series length (valid since table only used for sigma > 0.6)
#define GRAD_GAUSS_THRES 0.6f

// Scratch (no allocations allowed -> static device globals)
__device__ float  g_sineT[LL * WBINS];              // transposed sine_terms[l][w]
__device__ float2 g_table[(size_t)BB * (WBINS + 1)]; // per batch: (pdf_left, grad) for idx 0..1000
__device__ float2 g_params[BB];                     // (-1/sigma^2, cond flag)

// ---------------------------------------------------------------------------
// Kernel 0: transpose the first LL columns of sine_terms for coalesced access
// ---------------------------------------------------------------------------
__global__ void transpose_kernel(const float* __restrict__ sine_terms) {
    int l = blockIdx.x;       // 0..LL-1
    int w = threadIdx.x;      // 0..WBINS-1
    g_sineT[l * WBINS + w] = sine_terms[w * LSTRIDE + l];
}

// ---------------------------------------------------------------------------
// Kernel 1: build per-batch interpolation table.
// 8 batches per block, 256 threads; thread t (<250) owns bins 4t..4t+3.
// pdf is the UNNORMALIZED series (normalization cancels in grad/pdf ratio).
// Table entry for idx in [0,1000]:
//   left  = pdf_pad[idx],  grad = (pdf_pad[idx+1]-pdf_pad[idx]) / bw
// with pdf_pad = [pdf[0], pdf[0..999], pdf[998]].
// ---------------------------------------------------------------------------
__global__ void pdf_table_kernel(const float* __restrict__ sigmas,
                                 const float* __restrict__ omega_grid) {
    __shared__ float s_exp[8][LL];
    __shared__ float s_sig[8];
    __shared__ float s_pdf[WBINS];

    const int tid  = threadIdx.x;
    const int base = blockIdx.x * 8;

    if (tid < 8) {
        float sg = sigmas[base + tid];
        s_sig[tid] = sg;
        float s2 = sg * sg;
        g_params[base + tid] = make_float2(-1.0f / s2,
                                           (sg > GRAD_GAUSS_THRES) ? 1.0f : 0.0f);
    }
    if (tid < 8 * LL) {
        int g = tid >> 4;          // LL == 16
        int l = tid & (LL - 1);
        float sg  = sigmas[base + g];
        float arg = -0.5f * (float)(l * (l + 1)) * (sg * sg);
        s_exp[g][l] = expf(arg);
    }
    __syncthreads();

    float acc[8][4];
    if (tid < WBINS / 4) {
        #pragma unroll
        for (int g = 0; g < 8; g++)
            #pragma unroll
            for (int j = 0; j < 4; j++) acc[g][j] = 0.0f;

        // small terms first (l descending) for better summation accuracy
        #pragma unroll
        for (int l = LL - 1; l >= 0; l--) {
            float4 sv = *reinterpret_cast<const float4*>(&g_sineT[l * WBINS + 4 * tid]);
            #pragma unroll
            for (int g = 0; g < 8; g++) {
                float e = s_exp[g][l];
                acc[g][0] = fmaf(e, sv.x, acc[g][0]);
                acc[g][1] = fmaf(e, sv.y, acc[g][1]);
                acc[g][2] = fmaf(e, sv.z, acc[g][2]);
                acc[g][3] = fmaf(e, sv.w, acc[g][3]);
            }
        }
    }

    const float bw = omega_grid[1] - omega_grid[0];

    for (int g = 0; g < 8; g++) {
        if (!(s_sig[g] > GRAD_GAUSS_THRES)) continue;   // uniform across block

        __syncthreads();   // previous iteration's s_pdf readers done
        if (tid < WBINS / 4) {
            s_pdf[4 * tid + 0] = acc[g][0];
            s_pdf[4 * tid + 1] = acc[g][1];
            s_pdf[4 * tid + 2] = acc[g][2];
            s_pdf[4 * tid + 3] = acc[g][3];
        }
        __syncthreads();

        float2* trow = g_table + (size_t)(base + g) * (WBINS + 1);
        if (tid < WBINS / 4) {
            #pragma unroll
            for (int j = 0; j < 4; j++) {
                int idx = 4 * tid + j;
                float left  = (idx == 0) ? s_pdf[0] : s_pdf[idx - 1];
                float right = s_pdf[idx];
                trow[idx] = make_float2(left, __fdiv_rn(right - left, bw));
            }
        } else if (tid == WBINS / 4) {
            float left  = s_pdf[WBINS - 1];
            float right = s_pdf[WBINS - 2];
            trow[WBINS] = make_float2(left, __fdiv_rn(right - left, bw));
        }
    }
}

// ---------------------------------------------------------------------------
// Kernel 2: the B*N memory-bound evaluation. float4 vectorized.
// ---------------------------------------------------------------------------
__device__ __forceinline__ float eval_one(float omega, float bw,
                                          const float2* __restrict__ trow) {
    // IEEE division to bit-match reference's floor(omega/bw + 0.5) boundaries
    float q = floorf(__fdiv_rn(omega, bw) + 0.5f);
    int idx = (int)q;
    idx = max(0, min(idx, WBINS));
    float2 t = __ldg(&trow[idx]);
    float shift = omega - ((float)idx + 0.5f) * bw;
    float den = fmaf(shift, t.y, t.x);        // pdf_accurate (unnormalized)
    return __fdividef(t.y, den);              // scale-invariant ratio
}

__global__ void eval_kernel(const float* __restrict__ omegas,
                            const float* __restrict__ omega_grid,
                            float* __restrict__ out) {
    int i = blockIdx.x * blockDim.x + threadIdx.x;   // float4 index
    const float bw = omega_grid[1] - omega_grid[0];

    float4 om = __ldcs(reinterpret_cast<const float4*>(omegas) + i);
    int b = i >> 10;                                  // (4*i) / NN, NN=4096
    float2 p = g_params[b];

    float4 r;
    if (p.y > 0.5f) {
        const float2* trow = g_table + (size_t)b * (WBINS + 1);
        r.x = eval_one(om.x, bw, trow);
        r.y = eval_one(om.y, bw, trow);
        r.z = eval_one(om.z, bw, trow);
        r.w = eval_one(om.w, bw, trow);
    } else {
        r.x = om.x * p.x;
        r.y = om.y * p.x;
        r.z = om.z * p.x;
        r.w = om.w * p.x;
    }
    __stcs(reinterpret_cast<float4*>(out) + i, r);
}

// ---------------------------------------------------------------------------
extern "C" void kernel_launch(void* const* d_in, const int* in_sizes, int n_in,
                              void* d_out, int out_size) {
    const float* sigmas     = (const float*)d_in[0];   // [B]
    const float* omegas     = (const float*)d_in[1];   // [B, N]
    const float* omega_grid = (const float*)d_in[2];   // [WBINS]
    const float* sine_terms = (const float*)d_in[4];   // [WBINS, 101]

    transpose_kernel<<<LL, WBINS>>>(sine_terms);
    pdf_table_kernel<<<BB / 8, 256>>>(sigmas, omega_grid);

    const int total4 = BB * NN / 4;                    // 8,388,608
    eval_kernel<<<total4 / 256, 256>>>(omegas, omega_grid, (float*)d_out);
}

// round 2
// speedup vs baseline: 1.1535x; 1.1535x over previous
#include <cuda_runtime.h>
#include <math.h>

#define BB 8192
#define NN 4096
#define WBINS 1000
#define LSTRIDE 101        // L_CUTOFF + 1, row stride of sine_terms
#define LL 16              // truncated series (exp(-0.5*l(l+1)*0.36) < 5e-17 at l=14)
#define GRAD_GAUSS_THRES 0.6f
#define GPB 8              // batches per block
#define THREADS 512
#define PADROW 1004        // smem row stride (1002 used)

__device__ float g_sineT[LL * WBINS];   // transposed sine_terms[l][w]

// ---------------------------------------------------------------------------
// Kernel 0: transpose first LL columns of sine_terms (coalesced writes)
// ---------------------------------------------------------------------------
__global__ void transpose_kernel(const float* __restrict__ sine_terms) {
    int idx = blockIdx.x * blockDim.x + threadIdx.x;   // 0 .. LL*WBINS-1
    if (idx < LL * WBINS) {
        int l = idx / WBINS;
        int w = idx - l * WBINS;
        g_sineT[idx] = sine_terms[w * LSTRIDE + l];
    }
}

// ---------------------------------------------------------------------------
// Fused kernel: per block, build 8 batches' pdf_pad rows in SMEM, then
// evaluate those batches' 8*4096 omegas with SMEM gathers.
// pdf is UNNORMALIZED (normalization cancels in grad/pdf ratio).
// pdf_pad layout: row[0]=pdf[0], row[i]=pdf[i-1] (i=1..1000), row[1001]=pdf[998]
// ---------------------------------------------------------------------------
__global__ __launch_bounds__(THREADS)
void fused_kernel(const float* __restrict__ sigmas,
                  const float* __restrict__ omegas,
                  const float* __restrict__ omega_grid,
                  float* __restrict__ out) {
    __shared__ float  s_pdf[GPB][PADROW];
    __shared__ float  s_exp[GPB][LL];
    __shared__ float2 s_par[GPB];

    const int tid  = threadIdx.x;
    const int base = blockIdx.x * GPB;

    // ---- phase 1: per-batch params + series weights -------------------------
    if (tid < GPB) {
        float sg = sigmas[base + tid];
        s_par[tid] = make_float2(-1.0f / (sg * sg),
                                 (sg > GRAD_GAUSS_THRES) ? 1.0f : 0.0f);
    }
    if (tid < GPB * LL) {
        int g = tid >> 4;              // LL == 16
        int l = tid & (LL - 1);
        float sg = sigmas[base + g];
        s_exp[g][l] = expf(-0.5f * (float)(l * (l + 1)) * (sg * sg));
    }
    __syncthreads();

    // ---- phase 2: series -> pdf_pad rows in smem ----------------------------
    if (tid < WBINS / 2) {             // thread owns bins 2t, 2t+1
        float a0[GPB], a1[GPB];
        #pragma unroll
        for (int g = 0; g < GPB; g++) { a0[g] = 0.0f; a1[g] = 0.0f; }

        #pragma unroll
        for (int l = LL - 1; l >= 0; l--) {   // small terms first
            float2 sv = *reinterpret_cast<const float2*>(&g_sineT[l * WBINS + 2 * tid]);
            #pragma unroll
            for (int g = 0; g < GPB; g++) {
                float e = s_exp[g][l];
                a0[g] = fmaf(e, sv.x, a0[g]);
                a1[g] = fmaf(e, sv.y, a1[g]);
            }
        }
        #pragma unroll
        for (int g = 0; g < GPB; g++) {
            s_pdf[g][2 * tid + 1] = a0[g];
            s_pdf[g][2 * tid + 2] = a1[g];
            if (tid == 0)             s_pdf[g][0]    = a0[g];   // pdf[0]
            if (tid == WBINS / 2 - 1) s_pdf[g][1001] = a0[g];   // pdf[998]
        }
    }
    __syncthreads();

    // ---- phase 3: evaluate 8*4096 omegas ------------------------------------
    const float bw     = omega_grid[1] - omega_grid[0];
    const float inv_bw = 1.0f / bw;

    const float4* om4  = reinterpret_cast<const float4*>(omegas)
                         + (size_t)blockIdx.x * (GPB * NN / 4);
    float4*       out4 = reinterpret_cast<float4*>(out)
                         + (size_t)blockIdx.x * (GPB * NN / 4);

    #pragma unroll 4
    for (int j = 0; j < GPB * NN / 4 / THREADS; j++) {   // 16 iters
        int i  = j * THREADS + tid;
        int bl = i >> 10;                                // NN/4 = 1024 float4/batch
        float2 p  = s_par[bl];
        float4 om = __ldcs(om4 + i);
        float4 r;
        if (p.y > 0.5f) {
            const float* row = s_pdf[bl];
            #pragma unroll
            for (int c = 0; c < 4; c++) {
                float w = (&om.x)[c];
                float q = floorf(__fdiv_rn(w, bw) + 0.5f);
                int idx = min(max((int)q, 0), WBINS);
                float left  = row[idx];
                float right = row[idx + 1];
                float grad  = (right - left) * inv_bw;
                float shift = w - ((float)idx + 0.5f) * bw;
                (&r.x)[c] = __fdividef(grad, fmaf(shift, grad, left));
            }
        } else {
            r.x = om.x * p.x; r.y = om.y * p.x;
            r.z = om.z * p.x; r.w = om.w * p.x;
        }
        __stcs(out4 + i, r);
    }
}

// ---------------------------------------------------------------------------
extern "C" void kernel_launch(void* const* d_in, const int* in_sizes, int n_in,
                              void* d_out, int out_size) {
    const float* sigmas     = (const float*)d_in[0];   // [B]
    const float* omegas     = (const float*)d_in[1];   // [B, N]
    const float* omega_grid = (const float*)d_in[2];   // [WBINS]
    const float* sine_terms = (const float*)d_in[4];   // [WBINS, 101]

    transpose_kernel<<<(LL * WBINS + 255) / 256, 256>>>(sine_terms);
    fused_kernel<<<BB / GPB, THREADS>>>(sigmas, omegas, omega_grid, (float*)d_out);
}

// round 3
// speedup vs baseline: 1.2682x; 1.0995x over previous
#include <cuda_runtime.h>
#include <math.h>

#define BB 8192
#define NN 4096
#define WBINS 1000
#define LSTRIDE 101        // L_CUTOFF + 1, row stride of sine_terms
#define LL 16              // truncated series (exp(-0.5*l(l+1)*0.36) < 5e-17 at l=14)
#define GRAD_GAUSS_THRES 0.6f
#define GPB 8              // batches per block
#define THREADS 512
#define PADROW 1004        // smem row stride (1002 used)

__device__ float g_sineT[LL * WBINS];   // transposed sine_terms[l][w]

// ---------------------------------------------------------------------------
// Kernel 0: transpose first LL columns of sine_terms (coalesced writes)
// ---------------------------------------------------------------------------
__global__ void transpose_kernel(const float* __restrict__ sine_terms) {
    int idx = blockIdx.x * blockDim.x + threadIdx.x;   // 0 .. LL*WBINS-1
    if (idx < LL * WBINS) {
        int l = idx / WBINS;
        int w = idx - l * WBINS;
        g_sineT[idx] = sine_terms[w * LSTRIDE + l];
    }
}

// ---------------------------------------------------------------------------
// Fused kernel: per block, build 8 batches' pdf_pad rows in SMEM, then
// evaluate those batches' 8*4096 omegas with SMEM gathers.
// pdf is UNNORMALIZED (normalization cancels in the grad/pdf ratio).
// pdf_pad layout: row[0]=pdf[0], row[i]=pdf[i-1] (i=1..1000), row[1001]=pdf[998]
// ---------------------------------------------------------------------------
__global__ __launch_bounds__(THREADS, 3)
void fused_kernel(const float* __restrict__ sigmas,
                  const float* __restrict__ omegas,
                  const float* __restrict__ omega_grid,
                  float* __restrict__ out) {
    __shared__ float  s_pdf[GPB][PADROW];
    __shared__ float  s_expT[LL][GPB];    // transposed: row l holds 8 batch weights
    __shared__ float2 s_par[GPB];

    const int tid  = threadIdx.x;
    const int base = blockIdx.x * GPB;

    // ---- phase 1: per-batch params + series weights (transposed layout) ----
    if (tid < GPB) {
        float sg = sigmas[base + tid];
        s_par[tid] = make_float2(-1.0f / (sg * sg),
                                 (sg > GRAD_GAUSS_THRES) ? 1.0f : 0.0f);
    }
    if (tid < GPB * LL) {
        int l = tid >> 3;              // GPB == 8
        int g = tid & (GPB - 1);
        float sg = sigmas[base + g];
        s_expT[l][g] = expf(-0.5f * (float)(l * (l + 1)) * (sg * sg));
    }
    __syncthreads();

    // ---- phase 2: series -> pdf_pad rows in smem ----------------------------
    // thread t < 500 owns bins (2t, 2t+1); exp weights read as 2x LDS.128 per l
    if (tid < WBINS / 2) {
        float a0[GPB], a1[GPB];
        #pragma unroll
        for (int g = 0; g < GPB; g++) { a0[g] = 0.0f; a1[g] = 0.0f; }

        #pragma unroll
        for (int l = LL - 1; l >= 0; l--) {   // small terms first
            float2 sv = *reinterpret_cast<const float2*>(&g_sineT[l * WBINS + 2 * tid]);
            float e[GPB];
            *reinterpret_cast<float4*>(&e[0]) = *reinterpret_cast<const float4*>(&s_expT[l][0]);
            *reinterpret_cast<float4*>(&e[4]) = *reinterpret_cast<const float4*>(&s_expT[l][4]);
            #pragma unroll
            for (int g = 0; g < GPB; g++) {
                a0[g] = fmaf(e[g], sv.x, a0[g]);
                a1[g] = fmaf(e[g], sv.y, a1[g]);
            }
        }
        #pragma unroll
        for (int g = 0; g < GPB; g++) {
            s_pdf[g][2 * tid + 1] = a0[g];
            s_pdf[g][2 * tid + 2] = a1[g];
            if (tid == 0)             s_pdf[g][0]    = a0[g];   // pdf[0]
            if (tid == WBINS / 2 - 1) s_pdf[g][1001] = a0[g];   // pdf[998]
        }
    }
    __syncthreads();

    // ---- phase 3: evaluate 8*4096 omegas ------------------------------------
    const float bw     = omega_grid[1] - omega_grid[0];
    const float inv_bw = 1.0f / bw;

    const float4* om4  = reinterpret_cast<const float4*>(omegas)
                         + (size_t)blockIdx.x * (GPB * NN / 4);
    float4*       out4 = reinterpret_cast<float4*>(out)
                         + (size_t)blockIdx.x * (GPB * NN / 4);

    #pragma unroll 2
    for (int j = 0; j < GPB * NN / 4 / THREADS; j++) {   // 16 iters
        int i  = j * THREADS + tid;
        int bl = i >> 10;                                // NN/4 = 1024 float4/batch
        float2 p  = s_par[bl];
        float4 om = __ldcs(om4 + i);
        float4 r;
        if (p.y > 0.5f) {
            const float* row = s_pdf[bl];
            #pragma unroll
            for (int c = 0; c < 4; c++) {
                float w = (&om.x)[c];
                // IEEE div to bit-match reference's floor(w/bw + 0.5) boundaries
                int idx = __float2int_rd(__fdiv_rn(w, bw) + 0.5f);
                idx = min(max(idx, 0), WBINS);           // safety clamp (cheap)
                float left  = row[idx];
                float right = row[idx + 1];
                float grad  = (right - left) * inv_bw;
                float shift = w - ((float)idx + 0.5f) * bw;
                (&r.x)[c] = __fdividef(grad, fmaf(shift, grad, left));
            }
        } else {
            r.x = om.x * p.x; r.y = om.y * p.x;
            r.z = om.z * p.x; r.w = om.w * p.x;
        }
        __stcs(out4 + i, r);
    }
}

// ---------------------------------------------------------------------------
extern "C" void kernel_launch(void* const* d_in, const int* in_sizes, int n_in,
                              void* d_out, int out_size) {
    const float* sigmas     = (const float*)d_in[0];   // [B]
    const float* omegas     = (const float*)d_in[1];   // [B, N]
    const float* omega_grid = (const float*)d_in[2];   // [WBINS]
    const float* sine_terms = (const float*)d_in[4];   // [WBINS, 101]

    transpose_kernel<<<(LL * WBINS + 255) / 256, 256>>>(sine_terms);
    fused_kernel<<<BB / GPB, THREADS>>>(sigmas, omegas, omega_grid, (float*)d_out);
}

// round 4
// speedup vs baseline: 1.3753x; 1.0844x over previous
#include <cuda_runtime.h>
#include <math.h>

#define BB 8192
#define NN 4096
#define WBINS 1000
#define LSTRIDE 101        // L_CUTOFF + 1, row stride of sine_terms
#define LL 16              // truncated series (exp(-0.5*l(l+1)*0.36) < 5e-17 at l=14)
#define GRAD_GAUSS_THRES 0.6f
#define GPB 8              // batches per block
#define THREADS 512
#define SINE_STRIDE 1024   // padded row stride of g_sineT (zeros beyond WBINS)
#define TABROW 1002        // float2 entries per table row (1001 used)

__device__ float g_sineT[LL * SINE_STRIDE];

// ---------------------------------------------------------------------------
// Kernel 0: transpose first LL columns of sine_terms, zero-pad to stride 1024
// ---------------------------------------------------------------------------
__global__ void transpose_kernel(const float* __restrict__ sine_terms) {
    int idx = blockIdx.x * blockDim.x + threadIdx.x;   // 0 .. LL*1024-1
    int l = idx >> 10;
    int w = idx & (SINE_STRIDE - 1);
    g_sineT[idx] = (w < WBINS) ? sine_terms[w * LSTRIDE + l] : 0.0f;
}

// ---------------------------------------------------------------------------
// Fused kernel. Per block: build 8 batches' (left, grad) interpolation tables
// in SMEM from the truncated Legendre series (unnormalized pdf — the
// normalization cancels in grad/pdf), then evaluate 8*4096 omegas.
// Table entry idx (0..1000): left = pdf_pad[idx],
//   grad = (pdf_pad[idx+1] - pdf_pad[idx]) * inv_bw
// with pdf_pad = [pdf[0], pdf[0..999], pdf[998]].
// ---------------------------------------------------------------------------
__global__ __launch_bounds__(THREADS, 3)
void fused_kernel(const float* __restrict__ sigmas,
                  const float* __restrict__ omegas,
                  const float* __restrict__ omega_grid,
                  float* __restrict__ out) {
    extern __shared__ char smem_raw[];
    float2 (*s_tab)[TABROW] = reinterpret_cast<float2(*)[TABROW]>(smem_raw);   // 8*1002*8 B
    float* smem_f  = reinterpret_cast<float*>(smem_raw + GPB * TABROW * 8);
    float (*s_expT)[GPB] = reinterpret_cast<float(*)[GPB]>(smem_f);            // [LL][8]
    float (*s_edge)[GPB] = reinterpret_cast<float(*)[GPB]>(smem_f + LL * GPB); // [16][8]
    float2* s_par = reinterpret_cast<float2*>(smem_f + LL * GPB + 16 * GPB);   // [8]

    const int tid  = threadIdx.x;
    const int lane = tid & 31;
    const int wid  = tid >> 5;
    const int base = blockIdx.x * GPB;

    const float bw     = __ldg(&omega_grid[1]) - __ldg(&omega_grid[0]);
    const float inv_bw = 1.0f / bw;

    // ---- phase 1: per-batch params + series weights (transposed layout) ----
    if (tid < GPB) {
        float sg = sigmas[base + tid];
        s_par[tid] = make_float2(-1.0f / (sg * sg),
                                 (sg > GRAD_GAUSS_THRES) ? 1.0f : 0.0f);
    }
    if (tid < GPB * LL) {
        int l = tid >> 3;
        int g = tid & (GPB - 1);
        float sg = sigmas[base + g];
        s_expT[l][g] = expf(-0.5f * (float)(l * (l + 1)) * (sg * sg));
    }
    __syncthreads();

    // ---- phase 2: series (all 512 threads; thread t owns bins 2t, 2t+1) ----
    float a0[GPB], a1[GPB];
    #pragma unroll
    for (int g = 0; g < GPB; g++) { a0[g] = 0.0f; a1[g] = 0.0f; }

    #pragma unroll
    for (int l = LL - 1; l >= 0; l--) {   // small terms first
        float2 sv = *reinterpret_cast<const float2*>(&g_sineT[l * SINE_STRIDE + 2 * tid]);
        float e[GPB];
        *reinterpret_cast<float4*>(&e[0]) = *reinterpret_cast<const float4*>(&s_expT[l][0]);
        *reinterpret_cast<float4*>(&e[4]) = *reinterpret_cast<const float4*>(&s_expT[l][4]);
        #pragma unroll
        for (int g = 0; g < GPB; g++) {
            a0[g] = fmaf(e[g], sv.x, a0[g]);
            a1[g] = fmaf(e[g], sv.y, a1[g]);
        }
    }

    // per-warp edge values: warp w stores its lane-0 a0 (pdf[64w]) for warp w-1
    if (lane == 0) {
        #pragma unroll
        for (int g = 0; g < GPB; g++) s_edge[wid][g] = a0[g];
    }
    __syncthreads();

    // n0[g] = pdf[2t+2] (next thread's a0); t=499 overrides per pdf_pad[1001]=pdf[998]
    float n0[GPB];
    #pragma unroll
    for (int g = 0; g < GPB; g++)
        n0[g] = __shfl_down_sync(0xffffffffu, a0[g], 1);
    if (lane == 31 && wid < 15) {
        #pragma unroll
        for (int g = 0; g < GPB; g++) n0[g] = s_edge[wid + 1][g];
    }
    if (tid == WBINS / 2 - 1) {
        #pragma unroll
        for (int g = 0; g < GPB; g++) n0[g] = a0[g];
    }

    if (tid < WBINS / 2) {
        #pragma unroll
        for (int g = 0; g < GPB; g++) {
            s_tab[g][2 * tid + 1] = make_float2(a0[g], (a1[g] - a0[g]) * inv_bw);
            s_tab[g][2 * tid + 2] = make_float2(a1[g], (n0[g] - a1[g]) * inv_bw);
            if (tid == 0) s_tab[g][0] = make_float2(a0[g], 0.0f);
        }
    }
    __syncthreads();

    // ---- phase 3: evaluate 8*4096 omegas ------------------------------------
    const float4* om4  = reinterpret_cast<const float4*>(omegas)
                         + (size_t)blockIdx.x * (GPB * NN / 4);
    float4*       out4 = reinterpret_cast<float4*>(out)
                         + (size_t)blockIdx.x * (GPB * NN / 4);

    #pragma unroll 4
    for (int j = 0; j < GPB * NN / 4 / THREADS; j++) {   // 16 iters
        int i  = j * THREADS + tid;
        int bl = i >> 10;                                // NN/4 = 1024 float4/batch
        float2 p  = s_par[bl];
        float4 om = __ldcs(om4 + i);
        float4 r;
        if (p.y > 0.5f) {
            const float2* row = s_tab[bl];
            #pragma unroll
            for (int c = 0; c < 4; c++) {
                float w = (&om.x)[c];
                int idx = __float2int_rd(fmaf(w, inv_bw, 0.5f));
                idx = min(idx, WBINS);                   // w in [0,pi) => idx >= 0
                float2 t = row[idx];
                float shift = fmaf(-((float)idx + 0.5f), bw, w);
                (&r.x)[c] = __fdividef(t.y, fmaf(shift, t.y, t.x));
            }
        } else {
            r.x = om.x * p.x; r.y = om.y * p.x;
            r.z = om.z * p.x; r.w = om.w * p.x;
        }
        __stcs(out4 + i, r);
    }
}

// ---------------------------------------------------------------------------
#define FUSED_SMEM (GPB * TABROW * 8 + LL * GPB * 4 + 16 * GPB * 4 + GPB * 8)

extern "C" void kernel_launch(void* const* d_in, const int* in_sizes, int n_in,
                              void* d_out, int out_size) {
    const float* sigmas     = (const float*)d_in[0];   // [B]
    const float* omegas     = (const float*)d_in[1];   // [B, N]
    const float* omega_grid = (const float*)d_in[2];   // [WBINS]
    const float* sine_terms = (const float*)d_in[4];   // [WBINS, 101]

    cudaFuncSetAttribute(fused_kernel,
                         cudaFuncAttributeMaxDynamicSharedMemorySize, FUSED_SMEM);

    transpose_kernel<<<LL * SINE_STRIDE / 256, 256>>>(sine_terms);
    fused_kernel<<<BB / GPB, THREADS, FUSED_SMEM>>>(sigmas, omegas, omega_grid,
                                                    (float*)d_out);
}